// round 5
// baseline (speedup 1.0000x reference)
#include <cuda_runtime.h>
#include <stdint.h>

// Problem constants (fixed by reference setup_inputs)
#define MAX_ATOMS 500000
#define MAX_MOL   5000

// Scratch (no cudaMalloc allowed)
__device__ float g_qmol[MAX_MOL];
__device__ float g_qic[MAX_ATOMS];
__device__ float g_S[MAX_ATOMS];

// Cluster gather config
#define CLUSTER_N  16
#define SLICE_BITS 15
#define SLICE_SZ   (1 << SLICE_BITS)   // 32768 atoms/CTA -> 128KB smem
#define EDGE_TPB   512
#define EDGE_CTAS  128                 // 8 clusters of 16, fits same-die constraint

// ---------------- chi(r) ----------------
__device__ __forceinline__ float chi_term(float r) {
    float phi   = rsqrtf(fmaf(r, r, 1.0f));
    float inv_r = __fdividef(1.0f, r);
    float x  = r * 0.2f;                 // 2r / CUTOFF(=10)
    float chi;
    if (x < 1.0f) {
        float x3 = x * x * x;
        float f = fmaf(x3, fmaf(x, fmaf(x, -6.0f, 15.0f), -10.0f), 1.0f);
        chi = f * phi + (1.0f - f) * inv_r;
    } else {
        chi = inv_r;
    }
    return chi;
}

// ================= Fused prologue: one block per molecule =================
// Computes q_mol by block reduction (atoms of a mol are contiguous: batch = i/apm),
// then writes g_qic = qi - corr and g_S = 0.
__global__ void prologue_kernel(const float* __restrict__ qi,
                                const float* __restrict__ q_ref,
                                const int* __restrict__ Nv, int apm) {
    int m = blockIdx.x;
    long base = (long)m * apm;
    float v = 0.0f;
    for (int k = threadIdx.x; k < apm; k += blockDim.x) v += qi[base + k];
    // block reduce (128 threads = 4 warps)
    #pragma unroll
    for (int o = 16; o; o >>= 1) v += __shfl_down_sync(0xffffffffu, v, o);
    __shared__ float wsum[4];
    if ((threadIdx.x & 31) == 0) wsum[threadIdx.x >> 5] = v;
    __syncthreads();
    float sum = wsum[0] + wsum[1] + wsum[2] + wsum[3];
    float corr = (sum - q_ref[m]) / (float)Nv[m];
    for (int k = threadIdx.x; k < apm; k += blockDim.x) {
        g_qic[base + k] = qi[base + k] - corr;
        g_S[base + k]   = 0.0f;
    }
}

// ================= Fallback prologue (generic, 3 kernels) =================
__global__ void zero_kernel(int n_atoms, int n_mol) {
    int i = blockIdx.x * blockDim.x + threadIdx.x;
    if (i < n_atoms) g_S[i] = 0.0f;
    if (i < n_mol)   g_qmol[i] = 0.0f;
}

__global__ void qmol_kernel(const float* __restrict__ qi,
                            const int* __restrict__ batch, int n_atoms) {
    int t = blockIdx.x * blockDim.x + threadIdx.x;
    int i = t * 4;
    if (i + 3 < n_atoms) {
        float4 q = *reinterpret_cast<const float4*>(qi + i);
        int4   b = *reinterpret_cast<const int4*>(batch + i);
        if (b.x == b.y && b.x == b.z && b.x == b.w) {
            atomicAdd(&g_qmol[b.x], q.x + q.y + q.z + q.w);
        } else {
            atomicAdd(&g_qmol[b.x], q.x);
            atomicAdd(&g_qmol[b.y], q.y);
            atomicAdd(&g_qmol[b.z], q.z);
            atomicAdd(&g_qmol[b.w], q.w);
        }
    } else {
        for (int k = i; k < n_atoms; k++)
            atomicAdd(&g_qmol[batch[k]], qi[k]);
    }
}

__global__ void qic_kernel(const float* __restrict__ qi,
                           const int* __restrict__ batch,
                           const float* __restrict__ q_ref,
                           const int* __restrict__ Nv, int n_atoms) {
    int i = blockIdx.x * blockDim.x + threadIdx.x;
    if (i < n_atoms) {
        int b = batch[i];
        float corr = (g_qmol[b] - q_ref[b]) / (float)Nv[b];
        g_qic[i] = qi[i] - corr;
    }
}

// ================= DSMEM gather helper =================
__device__ __forceinline__ float dsmem_gather(uint32_t sbase, int j) {
    uint32_t addr = sbase + (((uint32_t)j & (SLICE_SZ - 1)) << 2);
    uint32_t rank = (uint32_t)j >> SLICE_BITS;
    uint32_t rem;
    asm("mapa.shared::cluster.u32 %0, %1, %2;" : "=r"(rem) : "r"(addr), "r"(rank));
    float v;
    asm volatile("ld.shared::cluster.f32 %0, [%1];" : "=f"(v) : "r"(rem));
    return v;
}

// ================= Edge kernel: cluster-resident gather table =================
__global__ void __launch_bounds__(EDGE_TPB, 1) __cluster_dims__(CLUSTER_N, 1, 1)
edge_cluster_kernel(const float* __restrict__ dist,
                    const int* __restrict__ idx0,
                    const int* __restrict__ idx1,
                    int n_edges, int n_atoms) {
    extern __shared__ float slice[];
    uint32_t rank;
    asm("mov.u32 %0, %%cluster_ctarank;" : "=r"(rank));

    // Load this CTA's 32768-atom slice of g_qic into smem
    int gbase = (int)(rank << SLICE_BITS);
    for (int k = threadIdx.x; k < SLICE_SZ; k += blockDim.x) {
        int g = gbase + k;
        slice[k] = (g < n_atoms) ? g_qic[g] : 0.0f;
    }
    uint32_t sbase;
    asm("{ .reg .u64 t; cvta.to.shared.u64 t, %1; cvt.u32.u64 %0, t; }"
        : "=r"(sbase) : "l"(slice));

    // All smem slices visible cluster-wide before gathering
    asm volatile("barrier.cluster.arrive.aligned;" ::: "memory");
    asm volatile("barrier.cluster.wait.aligned;" ::: "memory");

    int gtid   = blockIdx.x * blockDim.x + threadIdx.x;
    int stride = gridDim.x * blockDim.x;
    int nquads = n_edges >> 2;

    for (int q = gtid; q < nquads; q += stride) {
        int e = q * 4;
        float4 d = __ldcs(reinterpret_cast<const float4*>(dist + e));
        int4   a = __ldcs(reinterpret_cast<const int4*>(idx0 + e));
        int4   b = __ldcs(reinterpret_cast<const int4*>(idx1 + e));

        float t0 = dsmem_gather(sbase, b.x) * chi_term(d.x);
        float t1 = dsmem_gather(sbase, b.y) * chi_term(d.y);
        float t2 = dsmem_gather(sbase, b.z) * chi_term(d.z);
        float t3 = dsmem_gather(sbase, b.w) * chi_term(d.w);

        atomicAdd(&g_S[a.x], t0);
        atomicAdd(&g_S[a.y], t1);
        atomicAdd(&g_S[a.z], t2);
        atomicAdd(&g_S[a.w], t3);
    }
    // tail edges (n_edges % 4)
    for (int k = nquads * 4 + gtid; k < n_edges; k += stride) {
        float term = g_qic[idx1[k]] * chi_term(dist[k]);
        atomicAdd(&g_S[idx0[k]], term);
    }

    // No CTA may exit while peers can still read its smem
    asm volatile("barrier.cluster.arrive.aligned;" ::: "memory");
    asm volatile("barrier.cluster.wait.aligned;" ::: "memory");
}

// ================= Fallback edge kernel (no clusters) =================
__global__ void __launch_bounds__(256)
edge_kernel(const float* __restrict__ dist,
            const int* __restrict__ idx0,
            const int* __restrict__ idx1, int n_edges) {
    int t = blockIdx.x * blockDim.x + threadIdx.x;
    int e = t * 4;
    if (e + 3 < n_edges) {
        float4 d = *reinterpret_cast<const float4*>(dist + e);
        int4   a = *reinterpret_cast<const int4*>(idx0 + e);
        int4   b = *reinterpret_cast<const int4*>(idx1 + e);
        float t0 = __ldg(&g_qic[b.x]) * chi_term(d.x);
        float t1 = __ldg(&g_qic[b.y]) * chi_term(d.y);
        float t2 = __ldg(&g_qic[b.z]) * chi_term(d.z);
        float t3 = __ldg(&g_qic[b.w]) * chi_term(d.w);
        atomicAdd(&g_S[a.x], t0);
        atomicAdd(&g_S[a.y], t1);
        atomicAdd(&g_S[a.z], t2);
        atomicAdd(&g_S[a.w], t3);
    } else {
        for (int k = e; k < n_edges; k++) {
            float term = g_qic[idx1[k]] * chi_term(dist[k]);
            atomicAdd(&g_S[idx0[k]], term);
        }
    }
}

// ================= Epilogue: out = 0.5 * qi_c * S =================
__global__ void finish_kernel(float* __restrict__ out, int n_atoms) {
    int t = blockIdx.x * blockDim.x + threadIdx.x;
    int i = t * 4;
    if (i + 3 < n_atoms) {
        float4 q = *reinterpret_cast<const float4*>(g_qic + i);
        float4 s = *reinterpret_cast<const float4*>(g_S + i);
        float4 o;
        o.x = 0.5f * q.x * s.x;
        o.y = 0.5f * q.y * s.y;
        o.z = 0.5f * q.z * s.z;
        o.w = 0.5f * q.w * s.w;
        *reinterpret_cast<float4*>(out + i) = o;
    } else {
        for (int k = i; k < n_atoms; k++)
            out[k] = 0.5f * g_qic[k] * g_S[k];
    }
}

extern "C" void kernel_launch(void* const* d_in, const int* in_sizes, int n_in,
                              void* d_out, int out_size) {
    const float* qi       = (const float*)d_in[0];
    const float* dist     = (const float*)d_in[1];
    const int*   eidx     = (const int*)d_in[2];
    const float* q_ref    = (const float*)d_in[3];
    const int*   Nv       = (const int*)d_in[4];
    const int*   batch    = (const int*)d_in[5];
    float*       out      = (float*)d_out;

    int n_atoms = in_sizes[0];
    int n_edges = in_sizes[1];
    int n_mol   = in_sizes[3];

    const int* idx0 = eidx;
    const int* idx1 = eidx + n_edges;
    const int tpb = 256;

    // ---- prologue ----
    int apm = (n_mol > 0) ? n_atoms / n_mol : 0;
    bool uniform_mols = (n_mol > 0) && (apm * n_mol == n_atoms);
    if (uniform_mols) {
        prologue_kernel<<<n_mol, 128>>>(qi, q_ref, Nv, apm);
    } else {
        zero_kernel<<<(n_atoms + tpb - 1) / tpb, tpb>>>(n_atoms, n_mol);
        int nthreads = (n_atoms + 3) / 4;
        qmol_kernel<<<(nthreads + tpb - 1) / tpb, tpb>>>(qi, batch, n_atoms);
        qic_kernel<<<(n_atoms + tpb - 1) / tpb, tpb>>>(qi, batch, q_ref, Nv, n_atoms);
    }

    // ---- edge loop ----
    if (n_atoms <= CLUSTER_N * SLICE_SZ) {
        // Idempotent attribute sets (done on the correctness call before capture;
        // return values ignored deliberately).
        (void)cudaFuncSetAttribute(edge_cluster_kernel,
                                   cudaFuncAttributeNonPortableClusterSizeAllowed, 1);
        (void)cudaFuncSetAttribute(edge_cluster_kernel,
                                   cudaFuncAttributeMaxDynamicSharedMemorySize,
                                   SLICE_SZ * (int)sizeof(float));
        edge_cluster_kernel<<<EDGE_CTAS, EDGE_TPB, SLICE_SZ * sizeof(float)>>>(
            dist, idx0, idx1, n_edges, n_atoms);
    } else {
        int nthreads = (n_edges + 3) / 4;
        edge_kernel<<<(nthreads + tpb - 1) / tpb, tpb>>>(dist, idx0, idx1, n_edges);
    }

    // ---- epilogue ----
    {
        int nthreads = (n_atoms + 3) / 4;
        finish_kernel<<<(nthreads + tpb - 1) / tpb, tpb>>>(out, n_atoms);
    }
}

// round 7
// speedup vs baseline: 3.4655x; 3.4655x over previous
#include <cuda_runtime.h>
#include <stdint.h>

// Problem constants (fixed by reference setup_inputs)
#define MAX_ATOMS 500000
#define MAX_MOL   5000

// Scratch (no cudaMalloc allowed)
__device__ float g_qmol[MAX_MOL];
__device__ float g_qic[MAX_ATOMS];
__device__ float g_S[MAX_ATOMS];   // S[a] = sum over edges(idx0=a) of q_j * chi(r)

// ---------------- chi(r) ----------------
__device__ __forceinline__ float chi_term(float r) {
    // phi = 1/sqrt(r^2+1); f = cutoff_fn(2r, 10) i.e. x = r/5
    float phi   = rsqrtf(fmaf(r, r, 1.0f));
    float inv_r = __fdividef(1.0f, r);
    float x  = r * 0.2f;
    float chi;
    if (x < 1.0f) {
        float x3 = x * x * x;
        // f = 1 - 6x^5 + 15x^4 - 10x^3
        float f = fmaf(x3, fmaf(x, fmaf(x, -6.0f, 15.0f), -10.0f), 1.0f);
        chi = f * phi + (1.0f - f) * inv_r;
    } else {
        chi = inv_r;
    }
    return chi;
}

// ================= Fused prologue: one block per molecule =================
// q_mol by block reduction (atoms of a mol are contiguous), then qi_c and S=0.
__global__ void prologue_kernel(const float* __restrict__ qi,
                                const float* __restrict__ q_ref,
                                const int* __restrict__ Nv, int apm) {
    int m = blockIdx.x;
    long base = (long)m * apm;
    float v = 0.0f;
    for (int k = threadIdx.x; k < apm; k += blockDim.x) v += qi[base + k];
    #pragma unroll
    for (int o = 16; o; o >>= 1) v += __shfl_down_sync(0xffffffffu, v, o);
    __shared__ float wsum[4];
    if ((threadIdx.x & 31) == 0) wsum[threadIdx.x >> 5] = v;
    __syncthreads();
    float sum = wsum[0] + wsum[1] + wsum[2] + wsum[3];
    float corr = (sum - q_ref[m]) / (float)Nv[m];
    for (int k = threadIdx.x; k < apm; k += blockDim.x) {
        g_qic[base + k] = qi[base + k] - corr;
        g_S[base + k]   = 0.0f;
    }
}

// ================= Fallback prologue (generic) =================
__global__ void zero_kernel(int n_atoms, int n_mol) {
    int i = blockIdx.x * blockDim.x + threadIdx.x;
    if (i < n_atoms) g_S[i] = 0.0f;
    if (i < n_mol)   g_qmol[i] = 0.0f;
}

__global__ void qmol_kernel(const float* __restrict__ qi,
                            const int* __restrict__ batch, int n_atoms) {
    int t = blockIdx.x * blockDim.x + threadIdx.x;
    int i = t * 4;
    if (i + 3 < n_atoms) {
        float4 q = *reinterpret_cast<const float4*>(qi + i);
        int4   b = *reinterpret_cast<const int4*>(batch + i);
        if (b.x == b.y && b.x == b.z && b.x == b.w) {
            atomicAdd(&g_qmol[b.x], q.x + q.y + q.z + q.w);
        } else {
            atomicAdd(&g_qmol[b.x], q.x);
            atomicAdd(&g_qmol[b.y], q.y);
            atomicAdd(&g_qmol[b.z], q.z);
            atomicAdd(&g_qmol[b.w], q.w);
        }
    } else {
        for (int k = i; k < n_atoms; k++)
            atomicAdd(&g_qmol[batch[k]], qi[k]);
    }
}

__global__ void qic_kernel(const float* __restrict__ qi,
                           const int* __restrict__ batch,
                           const float* __restrict__ q_ref,
                           const int* __restrict__ Nv, int n_atoms) {
    int i = blockIdx.x * blockDim.x + threadIdx.x;
    if (i < n_atoms) {
        int b = batch[i];
        float corr = (g_qmol[b] - q_ref[b]) / (float)Nv[b];
        g_qic[i] = qi[i] - corr;
    }
}

// ================= Edge kernel: 8 edges/thread, L2 gathers =================
__global__ void __launch_bounds__(256)
edge_kernel(const float* __restrict__ dist,
            const int* __restrict__ idx0,
            const int* __restrict__ idx1, int n_edges) {
    int t = blockIdx.x * blockDim.x + threadIdx.x;
    int e = t * 8;
    if (e + 7 < n_edges) {
        // Issue all 6 streaming loads up front (evict-first: don't pollute L1,
        // the gathers below want the L1 capacity for g_qic).
        const float4 d0 = __ldcs(reinterpret_cast<const float4*>(dist + e));
        const float4 d1 = __ldcs(reinterpret_cast<const float4*>(dist + e + 4));
        const int4   a0 = __ldcs(reinterpret_cast<const int4*>(idx0 + e));
        const int4   a1 = __ldcs(reinterpret_cast<const int4*>(idx0 + e + 4));
        const int4   b0 = __ldcs(reinterpret_cast<const int4*>(idx1 + e));
        const int4   b1 = __ldcs(reinterpret_cast<const int4*>(idx1 + e + 4));

        // Gathers (read-only path, may hit L1)
        float q0 = __ldg(&g_qic[b0.x]);
        float q1 = __ldg(&g_qic[b0.y]);
        float q2 = __ldg(&g_qic[b0.z]);
        float q3 = __ldg(&g_qic[b0.w]);
        float q4 = __ldg(&g_qic[b1.x]);
        float q5 = __ldg(&g_qic[b1.y]);
        float q6 = __ldg(&g_qic[b1.z]);
        float q7 = __ldg(&g_qic[b1.w]);

        atomicAdd(&g_S[a0.x], q0 * chi_term(d0.x));
        atomicAdd(&g_S[a0.y], q1 * chi_term(d0.y));
        atomicAdd(&g_S[a0.z], q2 * chi_term(d0.z));
        atomicAdd(&g_S[a0.w], q3 * chi_term(d0.w));
        atomicAdd(&g_S[a1.x], q4 * chi_term(d1.x));
        atomicAdd(&g_S[a1.y], q5 * chi_term(d1.y));
        atomicAdd(&g_S[a1.z], q6 * chi_term(d1.z));
        atomicAdd(&g_S[a1.w], q7 * chi_term(d1.w));
    } else {
        for (int k = e; k < n_edges; k++) {
            float term = g_qic[idx1[k]] * chi_term(dist[k]);
            atomicAdd(&g_S[idx0[k]], term);
        }
    }
}

// ================= Epilogue: out = 0.5 * qi_c * S =================
__global__ void finish_kernel(float* __restrict__ out, int n_atoms) {
    int t = blockIdx.x * blockDim.x + threadIdx.x;
    int i = t * 4;
    if (i + 3 < n_atoms) {
        float4 q = *reinterpret_cast<const float4*>(g_qic + i);
        float4 s = *reinterpret_cast<const float4*>(g_S + i);
        float4 o;
        o.x = 0.5f * q.x * s.x;
        o.y = 0.5f * q.y * s.y;
        o.z = 0.5f * q.z * s.z;
        o.w = 0.5f * q.w * s.w;
        *reinterpret_cast<float4*>(out + i) = o;
    } else {
        for (int k = i; k < n_atoms; k++)
            out[k] = 0.5f * g_qic[k] * g_S[k];
    }
}

extern "C" void kernel_launch(void* const* d_in, const int* in_sizes, int n_in,
                              void* d_out, int out_size) {
    const float* qi       = (const float*)d_in[0];
    const float* dist     = (const float*)d_in[1];
    const int*   eidx     = (const int*)d_in[2];
    const float* q_ref    = (const float*)d_in[3];
    const int*   Nv       = (const int*)d_in[4];
    const int*   batch    = (const int*)d_in[5];
    float*       out      = (float*)d_out;

    int n_atoms = in_sizes[0];
    int n_edges = in_sizes[1];
    int n_mol   = in_sizes[3];

    const int* idx0 = eidx;
    const int* idx1 = eidx + n_edges;
    const int tpb = 256;

    // ---- prologue ----
    int apm = (n_mol > 0) ? n_atoms / n_mol : 0;
    bool uniform_mols = (n_mol > 0) && (apm * n_mol == n_atoms);
    if (uniform_mols) {
        prologue_kernel<<<n_mol, 128>>>(qi, q_ref, Nv, apm);
    } else {
        zero_kernel<<<(n_atoms + tpb - 1) / tpb, tpb>>>(n_atoms, n_mol);
        int nthreads = (n_atoms + 3) / 4;
        qmol_kernel<<<(nthreads + tpb - 1) / tpb, tpb>>>(qi, batch, n_atoms);
        qic_kernel<<<(n_atoms + tpb - 1) / tpb, tpb>>>(qi, batch, q_ref, Nv, n_atoms);
    }

    // ---- edge loop ----
    {
        int nthreads = (n_edges + 7) / 8;
        edge_kernel<<<(nthreads + tpb - 1) / tpb, tpb>>>(dist, idx0, idx1, n_edges);
    }

    // ---- epilogue ----
    {
        int nthreads = (n_atoms + 3) / 4;
        finish_kernel<<<(nthreads + tpb - 1) / tpb, tpb>>>(out, n_atoms);
    }
}